// round 1
// baseline (speedup 1.0000x reference)
#include <cuda_runtime.h>

// Problem constants
#define NTOK 4096          // 8 * 512 tokens (t=0 dropped)
#define DDIM 768
#define KCENT 8192
#define MT 64              // token tile
#define NT 128             // centroid tile
#define KT 16              // k-chunk
#define NTILES (KCENT / NT)  // 64 partial tiles per token row

// Scratch (allocation-free: __device__ globals)
__device__ float g_cnorm[KCENT];
__device__ float g_pd[NTILES * NTOK];
__device__ int   g_pi[NTILES * NTOK];

// ---------------------------------------------------------------------------
// Kernel 1: centroid squared norms. One block per centroid, 192 threads
// (768/4 float4 lanes).
// ---------------------------------------------------------------------------
__global__ void cnorm_kernel(const float* __restrict__ cent) {
    int k = blockIdx.x;
    const float4* row = (const float4*)(cent + (size_t)k * DDIM);
    float4 v = row[threadIdx.x];
    float s = v.x * v.x + v.y * v.y + v.z * v.z + v.w * v.w;
#pragma unroll
    for (int off = 16; off; off >>= 1)
        s += __shfl_down_sync(0xffffffffu, s, off);
    __shared__ float ws[6];
    if ((threadIdx.x & 31) == 0) ws[threadIdx.x >> 5] = s;
    __syncthreads();
    if (threadIdx.x == 0) {
        float t = 0.f;
#pragma unroll
        for (int w = 0; w < 6; w++) t += ws[w];
        g_cnorm[k] = t;
    }
}

// ---------------------------------------------------------------------------
// Kernel 2: fused distance GEMM + per-tile argmin.
// Block = 64 tokens x 128 centroids, 256 threads, thread tile 4x8.
// dist(m,n) = cnorm[n] - 2*dot(rep[m], cent[n])   (norm_rep dropped: constant
// per row, does not affect argmin).
// Partial (min_dist, argmin_idx) per 128-centroid tile written to scratch.
// ---------------------------------------------------------------------------
__global__ __launch_bounds__(256) void dist_kernel(
    const float* __restrict__ rep,    // [8, 513, 768]
    const float* __restrict__ cent)   // [8192, 768]
{
    __shared__ float As[KT][MT];   // k-major: conflict-free float4 frag reads
    __shared__ float Bs[KT][NT];

    const int mTile = blockIdx.x;           // 0..63
    const int nTile = blockIdx.y;           // 0..63
    const int mBase = mTile * MT;
    const int nBase = nTile * NT;
    const int b = mBase >> 9;               // batch index (MT divides 512)
    // token i -> rep row (b*513 + t + 1) = i + b + 1
    const float* Arep = rep + (size_t)(mBase + b + 1) * DDIM;
    const float* Bc   = cent + (size_t)nBase * DDIM;

    const int tid = threadIdx.x;
    const int tx = tid & 15;                // column group (8 cols)
    const int ty = tid >> 4;                // row group (4 rows)

    float acc[4][8];
#pragma unroll
    for (int r = 0; r < 4; r++)
#pragma unroll
        for (int c = 0; c < 8; c++) acc[r][c] = 0.f;

    const int arow = tid >> 2;              // 0..63
    const int akq  = tid & 3;               // which float4 within KT

    for (int k0 = 0; k0 < DDIM; k0 += KT) {
        // Load A tile (64 x 16), transpose into k-major smem
        float4 av = *(const float4*)(Arep + (size_t)arow * DDIM + k0 + akq * 4);
        As[akq * 4 + 0][arow] = av.x;
        As[akq * 4 + 1][arow] = av.y;
        As[akq * 4 + 2][arow] = av.z;
        As[akq * 4 + 3][arow] = av.w;
        // Load B tile (128 x 16), two rows per thread, transpose
#pragma unroll
        for (int h = 0; h < 2; h++) {
            int br = arow + h * 64;
            float4 bv = *(const float4*)(Bc + (size_t)br * DDIM + k0 + akq * 4);
            Bs[akq * 4 + 0][br] = bv.x;
            Bs[akq * 4 + 1][br] = bv.y;
            Bs[akq * 4 + 2][br] = bv.z;
            Bs[akq * 4 + 3][br] = bv.w;
        }
        __syncthreads();

#pragma unroll
        for (int kk = 0; kk < KT; kk++) {
            float4 a4  = *(const float4*)&As[kk][ty * 4];
            float4 b4a = *(const float4*)&Bs[kk][tx * 8];
            float4 b4b = *(const float4*)&Bs[kk][tx * 8 + 4];
            float av_[4] = {a4.x, a4.y, a4.z, a4.w};
            float bv_[8] = {b4a.x, b4a.y, b4a.z, b4a.w,
                            b4b.x, b4b.y, b4b.z, b4b.w};
#pragma unroll
            for (int r = 0; r < 4; r++)
#pragma unroll
                for (int c = 0; c < 8; c++)
                    acc[r][c] = fmaf(av_[r], bv_[c], acc[r][c]);
        }
        __syncthreads();
    }

    // Epilogue: dist = cnorm - 2*dot; per-row argmin over this 128-col tile.
    float cn[8];
#pragma unroll
    for (int c = 0; c < 8; c++) cn[c] = __ldg(&g_cnorm[nBase + tx * 8 + c]);

    float bd[4];
    int   bi[4];
#pragma unroll
    for (int r = 0; r < 4; r++) {
        float best = 3.4e38f;
        int besti = 0;
#pragma unroll
        for (int c = 0; c < 8; c++) {
            float dval = cn[c] - 2.f * acc[r][c];
            int gidx = nBase + tx * 8 + c;
            if (dval < best) { best = dval; besti = gidx; }   // ascending c => first-occurrence
        }
        bd[r] = best; bi[r] = besti;
    }
    // Reduce across the 16 tx lanes (width-16 shuffle segments align with tx)
#pragma unroll
    for (int off = 8; off; off >>= 1) {
#pragma unroll
        for (int r = 0; r < 4; r++) {
            float od = __shfl_down_sync(0xffffffffu, bd[r], off, 16);
            int   oi = __shfl_down_sync(0xffffffffu, bi[r], off, 16);
            if (od < bd[r] || (od == bd[r] && oi < bi[r])) { bd[r] = od; bi[r] = oi; }
        }
    }
    if (tx == 0) {
#pragma unroll
        for (int r = 0; r < 4; r++) {
            int m = mBase + ty * 4 + r;
            g_pd[(size_t)nTile * NTOK + m] = bd[r];
            g_pi[(size_t)nTile * NTOK + m] = bi[r];
        }
    }
}

// ---------------------------------------------------------------------------
// Kernel 3: reduce 64 partials per token -> final argmin; write token index
// (as float) and gather the winning centroid row.
// Output layout: [tokens(4096) | quantized(4096*768)] float32.
// ---------------------------------------------------------------------------
__global__ void reduce_kernel(const float* __restrict__ cent,
                              float* __restrict__ out) {
    const int i = blockIdx.x;   // token
    const int t = threadIdx.x;  // 256 threads
    __shared__ float sd[64];
    __shared__ int   si[64];
    if (t < 64) {
        sd[t] = g_pd[(size_t)t * NTOK + i];
        si[t] = g_pi[(size_t)t * NTOK + i];
    }
    __syncthreads();
    if (t < 32) {
        float d = sd[t]; int ix = si[t];
        float d2 = sd[t + 32]; int i2 = si[t + 32];
        if (d2 < d || (d2 == d && i2 < ix)) { d = d2; ix = i2; }
#pragma unroll
        for (int off = 16; off; off >>= 1) {
            float od = __shfl_down_sync(0xffffffffu, d, off);
            int   oi = __shfl_down_sync(0xffffffffu, ix, off);
            if (od < d || (od == d && oi < ix)) { d = od; ix = oi; }
        }
        if (t == 0) { si[0] = ix; }
    }
    __syncthreads();
    const int k = si[0];
    if (t == 0) out[i] = (float)k;
    const float4* src = (const float4*)(cent + (size_t)k * DDIM);
    float4* dst = (float4*)(out + NTOK + (size_t)i * DDIM);
    if (t < DDIM / 4) dst[t] = src[t];
}

// ---------------------------------------------------------------------------
extern "C" void kernel_launch(void* const* d_in, const int* in_sizes, int n_in,
                              void* d_out, int out_size) {
    const float* rep  = (const float*)d_in[0];   // [8,513,768]
    const float* cent = (const float*)d_in[1];   // [8192,768]
    float* out = (float*)d_out;

    cnorm_kernel<<<KCENT, 192>>>(cent);
    dim3 g(NTOK / MT, KCENT / NT);
    dist_kernel<<<g, 256>>>(rep, cent);
    reduce_kernel<<<NTOK, 256>>>(cent, out);
}

// round 3
// speedup vs baseline: 2.4481x; 2.4481x over previous
#include <cuda_runtime.h>
#include <cuda_bf16.h>
#include <cstdint>

// ---------------------------------------------------------------------------
// Problem constants
// ---------------------------------------------------------------------------
#define NTOK  4096          // 8 * 512 tokens (t=0 dropped)
#define DDIM  768
#define KCENT 8192

#define BM 128
#define BN 128
#define BK 32               // 32 bf16 = 64B rows
#define KCHUNKS (DDIM / BK) // 24
#define NPART (KCENT / 64)  // 128 partial argmin tiles (per-warp 64-col granularity)

// Stage layout: 3 A splits (128x64B) then 3 B splits (128x64B)
#define SPLIT_BYTES (128 * 64)
#define STAGE_BYTES (6 * SPLIT_BYTES)      // 49152
#define SMEM_BYTES  (2 * STAGE_BYTES)      // 98304

// ---------------------------------------------------------------------------
// Scratch (allocation-free: __device__ globals)
// ---------------------------------------------------------------------------
__device__ float g_cnorm[KCENT];
__device__ float g_pd[(size_t)NPART * NTOK];
__device__ int   g_pi[(size_t)NPART * NTOK];
__device__ __align__(16) unsigned short gA[3][(size_t)NTOK * DDIM];
__device__ __align__(16) unsigned short gB[3][(size_t)KCENT * DDIM];

// ---------------------------------------------------------------------------
// Helpers
// ---------------------------------------------------------------------------
__device__ __forceinline__ uint32_t smem_u32(const void* p) {
    uint32_t a;
    asm("{ .reg .u64 t; cvta.to.shared.u64 t, %1; cvt.u32.u64 %0, t; }" : "=r"(a) : "l"(p));
    return a;
}

// Swizzled smem offset for (row, 16B-chunk) in a 128x64B split buffer.
// Conflict-free for both cp.async writes and ldmatrix 8-row phases.
__device__ __forceinline__ uint32_t swoff(int row, int chunk) {
    return (uint32_t)(row * 64 + ((chunk ^ ((row >> 1) & 3)) << 4));
}

#define CP_ASYNC16(dst, src) \
    asm volatile("cp.async.cg.shared.global [%0], [%1], 16;" :: "r"(dst), "l"(src) : "memory")
#define CP_COMMIT() asm volatile("cp.async.commit_group;" ::: "memory")
#define CP_WAIT(n)  asm volatile("cp.async.wait_group %0;" :: "n"(n) : "memory")

__device__ __forceinline__ void ldsm4(uint32_t* r, uint32_t addr) {
    asm volatile("ldmatrix.sync.aligned.m8n8.x4.shared.b16 {%0,%1,%2,%3}, [%4];"
                 : "=r"(r[0]), "=r"(r[1]), "=r"(r[2]), "=r"(r[3]) : "r"(addr));
}

__device__ __forceinline__ void mma16816(float* c, const uint32_t* a, const uint32_t* b) {
    asm volatile(
        "mma.sync.aligned.m16n8k16.row.col.f32.bf16.bf16.f32 "
        "{%0,%1,%2,%3}, {%4,%5,%6,%7}, {%8,%9}, {%0,%1,%2,%3};"
        : "+f"(c[0]), "+f"(c[1]), "+f"(c[2]), "+f"(c[3])
        : "r"(a[0]), "r"(a[1]), "r"(a[2]), "r"(a[3]), "r"(b[0]), "r"(b[1]));
}

// ---------------------------------------------------------------------------
// bf16x3 split: x == b1 + b2 + b3 (~24 mantissa bits)
// ---------------------------------------------------------------------------
__device__ __forceinline__ void split3(float x, unsigned short& h1,
                                       unsigned short& h2, unsigned short& h3) {
    __nv_bfloat16 b1 = __float2bfloat16_rn(x);
    float r1 = x - __bfloat162float(b1);
    __nv_bfloat16 b2 = __float2bfloat16_rn(r1);
    float r2 = r1 - __bfloat162float(b2);
    __nv_bfloat16 b3 = __float2bfloat16_rn(r2);
    h1 = __bfloat16_as_ushort(b1);
    h2 = __bfloat16_as_ushort(b2);
    h3 = __bfloat16_as_ushort(b3);
}

__global__ void conv_cent(const float* __restrict__ cent) {
    int i = blockIdx.x * 256 + threadIdx.x;
    float4 v = ((const float4*)cent)[i];
    ushort4 u1, u2, u3;
    split3(v.x, u1.x, u2.x, u3.x);
    split3(v.y, u1.y, u2.y, u3.y);
    split3(v.z, u1.z, u2.z, u3.z);
    split3(v.w, u1.w, u2.w, u3.w);
    ((ushort4*)gB[0])[i] = u1;
    ((ushort4*)gB[1])[i] = u2;
    ((ushort4*)gB[2])[i] = u3;
}

__global__ void conv_rep(const float* __restrict__ rep) {
    int i = blockIdx.x * 256 + threadIdx.x;
    int row = i / (DDIM / 4);
    int c4  = i % (DDIM / 4);
    int srow = row + (row >> 9) + 1;                  // b*513 + t + 1
    float4 v = ((const float4*)rep)[(size_t)srow * (DDIM / 4) + c4];
    ushort4 u1, u2, u3;
    split3(v.x, u1.x, u2.x, u3.x);
    split3(v.y, u1.y, u2.y, u3.y);
    split3(v.z, u1.z, u2.z, u3.z);
    split3(v.w, u1.w, u2.w, u3.w);
    ((ushort4*)gA[0])[i] = u1;
    ((ushort4*)gA[1])[i] = u2;
    ((ushort4*)gA[2])[i] = u3;
}

__global__ void cnorm_kernel(const float* __restrict__ cent) {
    int k = blockIdx.x;
    const float4* row = (const float4*)(cent + (size_t)k * DDIM);
    float4 v = row[threadIdx.x];
    float s = v.x * v.x + v.y * v.y + v.z * v.z + v.w * v.w;
#pragma unroll
    for (int off = 16; off; off >>= 1) s += __shfl_down_sync(0xffffffffu, s, off);
    __shared__ float ws[6];
    if ((threadIdx.x & 31) == 0) ws[threadIdx.x >> 5] = s;
    __syncthreads();
    if (threadIdx.x == 0) {
        float t = 0.f;
#pragma unroll
        for (int w = 0; w < 6; w++) t += ws[w];
        g_cnorm[k] = t;
    }
}

// ---------------------------------------------------------------------------
// Main GEMM+argmin kernel. Grid (32, 64), 256 threads (8 warps).
// Warp grid 4(m) x 2(n): warp tile 32 x 64.
// ---------------------------------------------------------------------------
__global__ __launch_bounds__(256) void vq_mma_kernel() {
    extern __shared__ char smem[];
    const uint32_t sb = smem_u32(smem);

    const int tid  = threadIdx.x;
    const int wid  = tid >> 5;
    const int lane = tid & 31;
    const int warp_m = wid & 3;
    const int warp_n = wid >> 2;
    const int mBase = blockIdx.x * BM;
    const int nBase = blockIdx.y * BN;

    // ---- cp.async stage loader: 3072 x 16B per stage, 12 per thread ----
    auto load_stage = [&](int k0, int stage) {
        const uint32_t dstBase = sb + stage * STAGE_BYTES;
#pragma unroll
        for (int t = 0; t < 12; ++t) {
            int l   = tid + t * 256;     // 0..3071
            int arr = l >> 9;            // 0..5 (0-2: A splits, 3-5: B splits)
            int e   = l & 511;
            int row = e >> 2;
            int ch  = e & 3;
            const unsigned short* src;
            if (arr < 3)
                src = &gA[arr][(size_t)(mBase + row) * DDIM + k0 + ch * 8];
            else
                src = &gB[arr - 3][(size_t)(nBase + row) * DDIM + k0 + ch * 8];
            uint32_t dst = dstBase + arr * SPLIT_BYTES + swoff(row, ch);
            CP_ASYNC16(dst, src);
        }
    };

    float acc[2][8][4];
#pragma unroll
    for (int mt = 0; mt < 2; ++mt)
#pragma unroll
        for (int nt = 0; nt < 8; ++nt)
#pragma unroll
            for (int i = 0; i < 4; ++i) acc[mt][nt][i] = 0.f;

    // ldmatrix lane address components
    const int aRow = warp_m * 32 + (lane & 15);          // + mt*16
    const int aCh  = lane >> 4;                          // 0/1 within kstep
    const int bRow = warp_n * 64 + (lane & 7) + ((lane >> 4) << 3);  // + nt2*16
    const int bCh  = (lane >> 3) & 1;

    load_stage(0, 0);
    CP_COMMIT();

    int stage = 0;
    for (int it = 0; it < KCHUNKS; ++it) {
        if (it + 1 < KCHUNKS) {
            load_stage((it + 1) * BK, stage ^ 1);
            CP_COMMIT();
            CP_WAIT(1);
        } else {
            CP_WAIT(0);
        }
        __syncthreads();

        const uint32_t stA = sb + stage * STAGE_BYTES;
        const uint32_t stB = stA + 3 * SPLIT_BYTES;

#pragma unroll
        for (int ks = 0; ks < 2; ++ks) {
            uint32_t afr[3][2][4];
            uint32_t bfr[3][8][2];
#pragma unroll
            for (int s = 0; s < 3; ++s) {
#pragma unroll
                for (int mt = 0; mt < 2; ++mt)
                    ldsm4(afr[s][mt],
                          stA + s * SPLIT_BYTES + swoff(aRow + mt * 16, ks * 2 + aCh));
#pragma unroll
                for (int nt2 = 0; nt2 < 4; ++nt2) {
                    uint32_t r[4];
                    ldsm4(r, stB + s * SPLIT_BYTES + swoff(bRow + nt2 * 16, ks * 2 + bCh));
                    bfr[s][nt2 * 2][0]     = r[0];
                    bfr[s][nt2 * 2][1]     = r[1];
                    bfr[s][nt2 * 2 + 1][0] = r[2];
                    bfr[s][nt2 * 2 + 1][1] = r[3];
                }
            }
            // 6 split products with i+j <= 4 (bf16x3 emulated fp32)
            const int pa[6] = {0, 0, 1, 0, 1, 2};
            const int pb[6] = {0, 1, 0, 2, 1, 0};
#pragma unroll
            for (int p = 0; p < 6; ++p)
#pragma unroll
                for (int mt = 0; mt < 2; ++mt)
#pragma unroll
                    for (int nt = 0; nt < 8; ++nt)
                        mma16816(acc[mt][nt], afr[pa[p]][mt], bfr[pb[p]][nt]);
        }
        __syncthreads();
        stage ^= 1;
    }

    // ---- Epilogue: dist = cnorm - 2*dot; argmin over this warp's 64 cols ----
    const int groupID = lane >> 2;
    const int tIdx    = lane & 3;
    const int colBase = nBase + warp_n * 64;

    float cn[8][2];
#pragma unroll
    for (int nt = 0; nt < 8; ++nt) {
        cn[nt][0] = __ldg(&g_cnorm[colBase + nt * 8 + tIdx * 2 + 0]);
        cn[nt][1] = __ldg(&g_cnorm[colBase + nt * 8 + tIdx * 2 + 1]);
    }

#pragma unroll
    for (int h = 0; h < 4; ++h) {
        const int mt = h >> 1, rh = h & 1;
        float best = 3.4e38f;
        int besti = 0;
#pragma unroll
        for (int nt = 0; nt < 8; ++nt)
#pragma unroll
            for (int j = 0; j < 2; ++j) {
                float d = cn[nt][j] - 2.f * acc[mt][nt][rh * 2 + j];
                int gi = colBase + nt * 8 + tIdx * 2 + j;
                if (d < best) { best = d; besti = gi; }
            }
        // reduce across the 4 lanes of the group (tie -> lowest index)
#pragma unroll
        for (int x = 1; x < 4; x <<= 1) {
            float od = __shfl_xor_sync(0xffffffffu, best, x);
            int   oi = __shfl_xor_sync(0xffffffffu, besti, x);
            if (od < best || (od == best && oi < besti)) { best = od; besti = oi; }
        }
        if (tIdx == 0) {
            int rowG = mBase + warp_m * 32 + mt * 16 + groupID + rh * 8;
            int pidx = blockIdx.y * 2 + warp_n;
            g_pd[(size_t)pidx * NTOK + rowG] = best;
            g_pi[(size_t)pidx * NTOK + rowG] = besti;
        }
    }
}

// ---------------------------------------------------------------------------
// Final reduce over 128 partials + gather.
// Output layout: [tokens(4096) | quantized(4096*768)] float32.
// ---------------------------------------------------------------------------
__global__ void reduce_kernel(const float* __restrict__ cent,
                              float* __restrict__ out) {
    const int i = blockIdx.x;   // token
    const int t = threadIdx.x;  // 192 threads
    __shared__ float sd[128];
    __shared__ int   si[128];
    __shared__ int   sk;
    if (t < 128) {
        sd[t] = g_pd[(size_t)t * NTOK + i];
        si[t] = g_pi[(size_t)t * NTOK + i];
    }
    __syncthreads();
    if (t < 32) {
        float d = sd[t]; int ix = si[t];
#pragma unroll
        for (int q = 1; q < 4; ++q) {
            float od = sd[t + 32 * q]; int oi = si[t + 32 * q];
            if (od < d || (od == d && oi < ix)) { d = od; ix = oi; }
        }
#pragma unroll
        for (int off = 16; off; off >>= 1) {
            float od = __shfl_down_sync(0xffffffffu, d, off);
            int   oi = __shfl_down_sync(0xffffffffu, ix, off);
            if (od < d || (od == d && oi < ix)) { d = od; ix = oi; }
        }
        if (t == 0) sk = ix;
    }
    __syncthreads();
    const int k = sk;
    if (t == 0) out[i] = (float)k;
    const float4* src = (const float4*)(cent + (size_t)k * DDIM);
    float4* dst = (float4*)(out + NTOK + (size_t)i * DDIM);
    dst[t] = src[t];
}

// ---------------------------------------------------------------------------
extern "C" void kernel_launch(void* const* d_in, const int* in_sizes, int n_in,
                              void* d_out, int out_size) {
    const float* rep  = (const float*)d_in[0];   // [8,513,768]
    const float* cent = (const float*)d_in[1];   // [8192,768]
    float* out = (float*)d_out;

    cudaFuncSetAttribute(vq_mma_kernel, cudaFuncAttributeMaxDynamicSharedMemorySize,
                         SMEM_BYTES);

    conv_cent<<<(size_t)KCENT * DDIM / 4 / 256, 256>>>(cent);
    conv_rep<<<(size_t)NTOK * DDIM / 4 / 256, 256>>>(rep);
    cnorm_kernel<<<KCENT, 192>>>(cent);

    dim3 g(NTOK / BM, KCENT / BN);
    vq_mma_kernel<<<g, 256, SMEM_BYTES>>>();

    reduce_kernel<<<NTOK, 192>>>(cent, out);
}

// round 5
// speedup vs baseline: 5.8341x; 2.3832x over previous
#include <cuda_runtime.h>
#include <cuda_bf16.h>
#include <cuda_fp16.h>
#include <cstdint>

// ---------------------------------------------------------------------------
// Problem constants
// ---------------------------------------------------------------------------
#define NTOK  4096          // 8 * 512 tokens (t=0 dropped)
#define DDIM  768
#define KCENT 8192

#define BM 128
#define BN 128
#define BK 32               // 32 bf16 = 64B rows
#define KCHUNKS (DDIM / BK) // 24
#define NSTAGE 3
#define DELTA 8.0f          // prune threshold (approx-err worst case ~3)

#define ABYTES (128 * 64)            // one 128-row x 64B buffer
#define STAGE_BYTES (2 * ABYTES)     // A + B per stage = 16KB

// ---------------------------------------------------------------------------
// Scratch (allocation-free: __device__ globals)
// ---------------------------------------------------------------------------
__device__ float g_cnorm[KCENT];
__device__ __align__(16) unsigned short gA1[(size_t)NTOK * DDIM];   // bf16(rep)
__device__ __align__(16) unsigned short gB1[(size_t)KCENT * DDIM];  // bf16(cent)
__device__ __align__(16) __half g_approx[(size_t)NTOK * KCENT];     // 64MB approx dists

// ---------------------------------------------------------------------------
// Helpers
// ---------------------------------------------------------------------------
__device__ __forceinline__ uint32_t smem_u32(const void* p) {
    uint32_t a;
    asm("{ .reg .u64 t; cvta.to.shared.u64 t, %1; cvt.u32.u64 %0, t; }" : "=r"(a) : "l"(p));
    return a;
}

// Swizzled offset for (row, 16B-chunk) in a 128-row x 64B buffer.
__device__ __forceinline__ uint32_t swoff(int row, int chunk) {
    return (uint32_t)(row * 64 + ((chunk ^ ((row >> 1) & 3)) << 4));
}

#define CP_ASYNC16(dst, src) \
    asm volatile("cp.async.cg.shared.global [%0], [%1], 16;" :: "r"(dst), "l"(src) : "memory")
#define CP_COMMIT() asm volatile("cp.async.commit_group;" ::: "memory")
#define CP_WAIT(n)  asm volatile("cp.async.wait_group %0;" :: "n"(n) : "memory")

__device__ __forceinline__ void ldsm4(uint32_t* r, uint32_t addr) {
    asm volatile("ldmatrix.sync.aligned.m8n8.x4.shared.b16 {%0,%1,%2,%3}, [%4];"
                 : "=r"(r[0]), "=r"(r[1]), "=r"(r[2]), "=r"(r[3]) : "r"(addr));
}

__device__ __forceinline__ void mma16816(float* c, const uint32_t* a, const uint32_t* b) {
    asm volatile(
        "mma.sync.aligned.m16n8k16.row.col.f32.bf16.bf16.f32 "
        "{%0,%1,%2,%3}, {%4,%5,%6,%7}, {%8,%9}, {%0,%1,%2,%3};"
        : "+f"(c[0]), "+f"(c[1]), "+f"(c[2]), "+f"(c[3])
        : "r"(a[0]), "r"(a[1]), "r"(a[2]), "r"(a[3]), "r"(b[0]), "r"(b[1]));
}

// ---------------------------------------------------------------------------
// Conversion kernels
// ---------------------------------------------------------------------------
// rep (dropping t=0 rows) -> dense [4096 x 768] bf16
__global__ void conv_rep1(const float* __restrict__ rep) {
    int i = blockIdx.x * 256 + threadIdx.x;           // over NTOK*DDIM/4
    int row = i / (DDIM / 4);
    int c4  = i % (DDIM / 4);
    int srow = row + (row >> 9) + 1;                  // b*513 + t + 1
    float4 v = ((const float4*)rep)[(size_t)srow * (DDIM / 4) + c4];
    __nv_bfloat162 lo = __floats2bfloat162_rn(v.x, v.y);
    __nv_bfloat162 hi = __floats2bfloat162_rn(v.z, v.w);
    uint2 u;
    u.x = reinterpret_cast<uint32_t&>(lo);
    u.y = reinterpret_cast<uint32_t&>(hi);
    ((uint2*)gA1)[i] = u;
}

// centroids -> bf16, fused with fp32 squared-norm (one warp per centroid).
// DDIM/4 = 192 float4 per row -> 6 iterations of 32 lanes.
__global__ void conv_cent_norm(const float* __restrict__ cent) {
    int k = blockIdx.x * 8 + (threadIdx.x >> 5);
    int lane = threadIdx.x & 31;
    const float4* src = (const float4*)(cent + (size_t)k * DDIM);
    uint2* dst = (uint2*)(gB1 + (size_t)k * DDIM);
    float s = 0.f;
#pragma unroll
    for (int j = 0; j < 6; ++j) {                     // FIX: 6 (was 3) -> full 192 float4
        int q = lane + 32 * j;
        float4 v = src[q];
        __nv_bfloat162 lo = __floats2bfloat162_rn(v.x, v.y);
        __nv_bfloat162 hi = __floats2bfloat162_rn(v.z, v.w);
        uint2 u;
        u.x = reinterpret_cast<uint32_t&>(lo);
        u.y = reinterpret_cast<uint32_t&>(hi);
        dst[q] = u;
        s += v.x * v.x + v.y * v.y + v.z * v.z + v.w * v.w;
    }
#pragma unroll
    for (int off = 16; off; off >>= 1) s += __shfl_down_sync(0xffffffffu, s, off);
    if (lane == 0) g_cnorm[k] = s;
}

// ---------------------------------------------------------------------------
// Phase 1: bf16 GEMM -> approx distances (fp16). Grid (32, 64), 256 threads.
// Warp grid 4(m) x 2(n): warp tile 32 x 64. 3-stage cp.async pipeline.
// ---------------------------------------------------------------------------
__global__ __launch_bounds__(256, 2) void vq_gemm() {
    __shared__ __align__(16) char smem[NSTAGE * STAGE_BYTES];
    const uint32_t sb = smem_u32(smem);

    const int tid  = threadIdx.x;
    const int wid  = tid >> 5;
    const int lane = tid & 31;
    const int warp_m = wid & 3;
    const int warp_n = wid >> 2;
    const int mBase = blockIdx.x * BM;
    const int nBase = blockIdx.y * BN;

    auto load_stage = [&](int k0, int st) {
        const uint32_t base = sb + st * STAGE_BYTES;
#pragma unroll
        for (int t = 0; t < 4; ++t) {
            int l = tid + t * 256;      // 0..1023
            int part = l >> 9;          // 0: A, 1: B
            int e = l & 511;
            int row = e >> 2;
            int ch = e & 3;
            const unsigned short* src = part
                ? &gB1[(size_t)(nBase + row) * DDIM + k0 + ch * 8]
                : &gA1[(size_t)(mBase + row) * DDIM + k0 + ch * 8];
            CP_ASYNC16(base + part * ABYTES + swoff(row, ch), src);
        }
    };

    float acc[2][8][4];
#pragma unroll
    for (int mt = 0; mt < 2; ++mt)
#pragma unroll
        for (int nt = 0; nt < 8; ++nt)
#pragma unroll
            for (int i = 0; i < 4; ++i) acc[mt][nt][i] = 0.f;

    const int aRow = warp_m * 32 + (lane & 15);
    const int aCh  = lane >> 4;
    const int bRow = warp_n * 64 + (lane & 7) + ((lane >> 4) << 3);
    const int bCh  = (lane >> 3) & 1;

    load_stage(0, 0); CP_COMMIT();
    load_stage(BK, 1); CP_COMMIT();

    for (int it = 0; it < KCHUNKS; ++it) {
        if (it + 1 < KCHUNKS) { CP_WAIT(1); } else { CP_WAIT(0); }
        __syncthreads();
        if (it + 2 < KCHUNKS) {
            load_stage((it + 2) * BK, (it + 2) % NSTAGE);
            CP_COMMIT();
        }
        const uint32_t stA = sb + (it % NSTAGE) * STAGE_BYTES;
        const uint32_t stB = stA + ABYTES;

#pragma unroll
        for (int ks = 0; ks < 2; ++ks) {
            uint32_t afr[2][4];
            uint32_t bfr[8][2];
#pragma unroll
            for (int mt = 0; mt < 2; ++mt)
                ldsm4(afr[mt], stA + swoff(aRow + mt * 16, ks * 2 + aCh));
#pragma unroll
            for (int nt2 = 0; nt2 < 4; ++nt2) {
                uint32_t r[4];
                ldsm4(r, stB + swoff(bRow + nt2 * 16, ks * 2 + bCh));
                bfr[nt2 * 2][0]     = r[0];
                bfr[nt2 * 2][1]     = r[1];
                bfr[nt2 * 2 + 1][0] = r[2];
                bfr[nt2 * 2 + 1][1] = r[3];
            }
#pragma unroll
            for (int mt = 0; mt < 2; ++mt)
#pragma unroll
                for (int nt = 0; nt < 8; ++nt)
                    mma16816(acc[mt][nt], afr[mt], bfr[nt]);
        }
        __syncthreads();
    }

    // Epilogue: approx dist = cnorm - 2*dot -> fp16 matrix
    const int groupID = lane >> 2;
    const int tIdx    = lane & 3;
    const int colBase = nBase + warp_n * 64;

    float cn[8][2];
#pragma unroll
    for (int nt = 0; nt < 8; ++nt) {
        cn[nt][0] = __ldg(&g_cnorm[colBase + nt * 8 + tIdx * 2 + 0]);
        cn[nt][1] = __ldg(&g_cnorm[colBase + nt * 8 + tIdx * 2 + 1]);
    }
#pragma unroll
    for (int mt = 0; mt < 2; ++mt)
#pragma unroll
        for (int rh = 0; rh < 2; ++rh) {
            int row = mBase + warp_m * 32 + mt * 16 + rh * 8 + groupID;
            __half2* dst = (__half2*)(g_approx + (size_t)row * KCENT + colBase);
#pragma unroll
            for (int nt = 0; nt < 8; ++nt) {
                float d0 = cn[nt][0] - 2.f * acc[mt][nt][rh * 2 + 0];
                float d1 = cn[nt][1] - 2.f * acc[mt][nt][rh * 2 + 1];
                dst[nt * 4 + tIdx] = __floats2half2_rn(d0, d1);
            }
        }
}

// ---------------------------------------------------------------------------
// Phase 2: per-token scan + exact fp32 rescue + gather.
// Output layout: [tokens(4096) | quantized(4096*768)] float32.
// ---------------------------------------------------------------------------
__global__ __launch_bounds__(256) void finalize(const float* __restrict__ rep,
                                                const float* __restrict__ cent,
                                                float* __restrict__ out) {
    __shared__ __align__(16) __half sd[KCENT];
    __shared__ __align__(16) float srep[DDIM];
    __shared__ float wmin[8];
    __shared__ float sthr;
    __shared__ unsigned long long sbest;

    const int i = blockIdx.x;
    const int t = threadIdx.x;

    // Load approx row (16KB) + rep row (3KB) into smem
    const uint4* arow = (const uint4*)(g_approx + (size_t)i * KCENT);
    uint4* sdv = (uint4*)sd;
#pragma unroll
    for (int q = 0; q < 4; ++q) sdv[t + q * 256] = arow[t + q * 256];
    const int srow = i + (i >> 9) + 1;
    if (t < DDIM / 4)
        ((float4*)srep)[t] = ((const float4*)(rep + (size_t)srow * DDIM))[t];
    if (t == 0) sbest = ~0ull;
    __syncthreads();

    // Block min of approx distances
    float m = 1e30f;
    const __half2* sh2 = ((const __half2*)sd) + t * 16;
#pragma unroll
    for (int q = 0; q < 16; ++q) {
        float2 f = __half22float2(sh2[q]);
        m = fminf(m, fminf(f.x, f.y));
    }
#pragma unroll
    for (int off = 16; off; off >>= 1)
        m = fminf(m, __shfl_xor_sync(0xffffffffu, m, off));
    if ((t & 31) == 0) wmin[t >> 5] = m;
    __syncthreads();
    if (t == 0) {
        float mm = wmin[0];
#pragma unroll
        for (int w = 1; w < 8; ++w) mm = fminf(mm, wmin[w]);
        sthr = mm + DELTA;
    }
    __syncthreads();
    const float thr = sthr;

    // Exact fp32 distance for candidates; lexicographic (dist, idx) min
    for (int j = 0; j < 32; ++j) {
        const int k = t * 32 + j;
        float v = __half2float(sd[k]);
        if (v <= thr) {
            const float4* c4 = (const float4*)(cent + (size_t)k * DDIM);
            float s0 = 0.f, s1 = 0.f, s2 = 0.f, s3 = 0.f;
#pragma unroll 8
            for (int q = 0; q < DDIM / 4; ++q) {
                float4 cv = __ldg(&c4[q]);
                float4 rv = ((const float4*)srep)[q];
                s0 = fmaf(rv.x, cv.x, s0);
                s1 = fmaf(rv.y, cv.y, s1);
                s2 = fmaf(rv.z, cv.z, s2);
                s3 = fmaf(rv.w, cv.w, s3);
            }
            float d = __ldg(&g_cnorm[k]) - 2.f * ((s0 + s1) + (s2 + s3));
            unsigned int u = __float_as_uint(d);
            unsigned int key = (u & 0x80000000u) ? ~u : (u | 0x80000000u);
            unsigned long long pk = ((unsigned long long)key << 32) | (unsigned int)k;
            atomicMin(&sbest, pk);
        }
    }
    __syncthreads();

    const int kbest = (int)(sbest & 0xffffffffu);
    if (t == 0) out[i] = (float)kbest;
    if (t < DDIM / 4)
        ((float4*)(out + NTOK + (size_t)i * DDIM))[t] =
            ((const float4*)(cent + (size_t)kbest * DDIM))[t];
}

// ---------------------------------------------------------------------------
extern "C" void kernel_launch(void* const* d_in, const int* in_sizes, int n_in,
                              void* d_out, int out_size) {
    const float* rep  = (const float*)d_in[0];   // [8,513,768]
    const float* cent = (const float*)d_in[1];   // [8192,768]
    float* out = (float*)d_out;

    conv_rep1<<<(size_t)NTOK * DDIM / 4 / 256, 256>>>(rep);
    conv_cent_norm<<<KCENT / 8, 256>>>(cent);

    dim3 g(NTOK / BM, KCENT / BN);
    vq_gemm<<<g, 256>>>();

    finalize<<<NTOK, 256>>>(rep, cent, out);
}

// round 6
// speedup vs baseline: 9.7783x; 1.6761x over previous
#include <cuda_runtime.h>
#include <cuda_bf16.h>
#include <cstdint>

// ---------------------------------------------------------------------------
// Problem constants
// ---------------------------------------------------------------------------
#define NTOK  4096          // 8 * 512 tokens (t=0 dropped)
#define DDIM  768
#define KCENT 8192

#define BM 128
#define BN 128
#define BK 32               // 32 bf16 = 64B rows
#define KCHUNKS (DDIM / BK) // 24
#define NSTAGE 3
#define DELTA 8.0f          // prune threshold (bf16 approx err worst-case ~2)
#define NREG 128            // 64-centroid regions per token
#define CAP 256             // extras capacity per token

#define ABYTES (128 * 64)            // one 128-row x 64B buffer
#define STAGE_BYTES (2 * ABYTES)     // A + B per stage = 16KB

// ---------------------------------------------------------------------------
// Scratch (allocation-free: __device__ globals)
// ---------------------------------------------------------------------------
__device__ float g_cnorm[KCENT];
__device__ __align__(16) unsigned short gA1[(size_t)NTOK * DDIM];   // bf16(rep)
__device__ __align__(16) unsigned short gB1[(size_t)KCENT * DDIM];  // bf16(cent)
__device__ float g_pd[(size_t)NTOK * NREG];      // per-region approx min
__device__ int   g_pi[(size_t)NTOK * NREG];      // per-region approx argmin
__device__ int   g_cnt[NTOK];                    // extras counter
__device__ float g_cv[(size_t)NTOK * CAP];       // extras approx value
__device__ int   g_ci[(size_t)NTOK * CAP];       // extras index

// ---------------------------------------------------------------------------
// Helpers
// ---------------------------------------------------------------------------
__device__ __forceinline__ uint32_t smem_u32(const void* p) {
    uint32_t a;
    asm("{ .reg .u64 t; cvta.to.shared.u64 t, %1; cvt.u32.u64 %0, t; }" : "=r"(a) : "l"(p));
    return a;
}

__device__ __forceinline__ uint32_t swoff(int row, int chunk) {
    return (uint32_t)(row * 64 + ((chunk ^ ((row >> 1) & 3)) << 4));
}

#define CP_ASYNC16(dst, src) \
    asm volatile("cp.async.cg.shared.global [%0], [%1], 16;" :: "r"(dst), "l"(src) : "memory")
#define CP_COMMIT() asm volatile("cp.async.commit_group;" ::: "memory")
#define CP_WAIT(n)  asm volatile("cp.async.wait_group %0;" :: "n"(n) : "memory")

__device__ __forceinline__ void ldsm4(uint32_t* r, uint32_t addr) {
    asm volatile("ldmatrix.sync.aligned.m8n8.x4.shared.b16 {%0,%1,%2,%3}, [%4];"
                 : "=r"(r[0]), "=r"(r[1]), "=r"(r[2]), "=r"(r[3]) : "r"(addr));
}

__device__ __forceinline__ void mma16816(float* c, const uint32_t* a, const uint32_t* b) {
    asm volatile(
        "mma.sync.aligned.m16n8k16.row.col.f32.bf16.bf16.f32 "
        "{%0,%1,%2,%3}, {%4,%5,%6,%7}, {%8,%9}, {%0,%1,%2,%3};"
        : "+f"(c[0]), "+f"(c[1]), "+f"(c[2]), "+f"(c[3])
        : "r"(a[0]), "r"(a[1]), "r"(a[2]), "r"(a[3]), "r"(b[0]), "r"(b[1]));
}

// ---------------------------------------------------------------------------
// Init / conversion kernels
// ---------------------------------------------------------------------------
__global__ void zero_cnt() {
    g_cnt[blockIdx.x * 256 + threadIdx.x] = 0;
}

// rep (dropping t=0 rows) -> dense [4096 x 768] bf16
__global__ void conv_rep1(const float* __restrict__ rep) {
    int i = blockIdx.x * 256 + threadIdx.x;           // over NTOK*DDIM/4
    int row = i / (DDIM / 4);
    int c4  = i % (DDIM / 4);
    int srow = row + (row >> 9) + 1;                  // b*513 + t + 1
    float4 v = ((const float4*)rep)[(size_t)srow * (DDIM / 4) + c4];
    __nv_bfloat162 lo = __floats2bfloat162_rn(v.x, v.y);
    __nv_bfloat162 hi = __floats2bfloat162_rn(v.z, v.w);
    uint2 u;
    u.x = reinterpret_cast<uint32_t&>(lo);
    u.y = reinterpret_cast<uint32_t&>(hi);
    ((uint2*)gA1)[i] = u;
}

// centroids -> bf16, fused with fp32 squared-norm (one warp per centroid)
__global__ void conv_cent_norm(const float* __restrict__ cent) {
    int k = blockIdx.x * 8 + (threadIdx.x >> 5);
    int lane = threadIdx.x & 31;
    const float4* src = (const float4*)(cent + (size_t)k * DDIM);
    uint2* dst = (uint2*)(gB1 + (size_t)k * DDIM);
    float s = 0.f;
#pragma unroll
    for (int j = 0; j < 6; ++j) {                     // 6*32 = 192 float4 = 768
        int q = lane + 32 * j;
        float4 v = src[q];
        __nv_bfloat162 lo = __floats2bfloat162_rn(v.x, v.y);
        __nv_bfloat162 hi = __floats2bfloat162_rn(v.z, v.w);
        uint2 u;
        u.x = reinterpret_cast<uint32_t&>(lo);
        u.y = reinterpret_cast<uint32_t&>(hi);
        dst[q] = u;
        s += v.x * v.x + v.y * v.y + v.z * v.z + v.w * v.w;
    }
#pragma unroll
    for (int off = 16; off; off >>= 1) s += __shfl_down_sync(0xffffffffu, s, off);
    if (lane == 0) g_cnorm[k] = s;
}

// ---------------------------------------------------------------------------
// Phase 1: bf16 GEMM; epilogue emits per-region (min, argmin) + extras list.
// Grid (32, 64), 256 threads. Warp grid 4(m) x 2(n): warp tile 32 x 64.
// ---------------------------------------------------------------------------
__global__ __launch_bounds__(256, 2) void vq_gemm() {
    __shared__ __align__(16) char smem[NSTAGE * STAGE_BYTES];
    const uint32_t sb = smem_u32(smem);

    const int tid  = threadIdx.x;
    const int wid  = tid >> 5;
    const int lane = tid & 31;
    const int warp_m = wid & 3;
    const int warp_n = wid >> 2;
    const int mBase = blockIdx.x * BM;
    const int nBase = blockIdx.y * BN;

    auto load_stage = [&](int k0, int st) {
        const uint32_t base = sb + st * STAGE_BYTES;
#pragma unroll
        for (int t = 0; t < 4; ++t) {
            int l = tid + t * 256;
            int part = l >> 9;          // 0: A, 1: B
            int e = l & 511;
            int row = e >> 2;
            int ch = e & 3;
            const unsigned short* src = part
                ? &gB1[(size_t)(nBase + row) * DDIM + k0 + ch * 8]
                : &gA1[(size_t)(mBase + row) * DDIM + k0 + ch * 8];
            CP_ASYNC16(base + part * ABYTES + swoff(row, ch), src);
        }
    };

    float acc[2][8][4];
#pragma unroll
    for (int mt = 0; mt < 2; ++mt)
#pragma unroll
        for (int nt = 0; nt < 8; ++nt)
#pragma unroll
            for (int i = 0; i < 4; ++i) acc[mt][nt][i] = 0.f;

    const int aRow = warp_m * 32 + (lane & 15);
    const int aCh  = lane >> 4;
    const int bRow = warp_n * 64 + (lane & 7) + ((lane >> 4) << 3);
    const int bCh  = (lane >> 3) & 1;

    load_stage(0, 0); CP_COMMIT();
    load_stage(BK, 1); CP_COMMIT();

    for (int it = 0; it < KCHUNKS; ++it) {
        if (it + 1 < KCHUNKS) { CP_WAIT(1); } else { CP_WAIT(0); }
        __syncthreads();
        if (it + 2 < KCHUNKS) {
            load_stage((it + 2) * BK, (it + 2) % NSTAGE);
            CP_COMMIT();
        }
        const uint32_t stA = sb + (it % NSTAGE) * STAGE_BYTES;
        const uint32_t stB = stA + ABYTES;

#pragma unroll
        for (int ks = 0; ks < 2; ++ks) {
            uint32_t afr[2][4];
            uint32_t bfr[8][2];
#pragma unroll
            for (int mt = 0; mt < 2; ++mt)
                ldsm4(afr[mt], stA + swoff(aRow + mt * 16, ks * 2 + aCh));
#pragma unroll
            for (int nt2 = 0; nt2 < 4; ++nt2) {
                uint32_t r[4];
                ldsm4(r, stB + swoff(bRow + nt2 * 16, ks * 2 + bCh));
                bfr[nt2 * 2][0]     = r[0];
                bfr[nt2 * 2][1]     = r[1];
                bfr[nt2 * 2 + 1][0] = r[2];
                bfr[nt2 * 2 + 1][1] = r[3];
            }
#pragma unroll
            for (int mt = 0; mt < 2; ++mt)
#pragma unroll
                for (int nt = 0; nt < 8; ++nt)
                    mma16816(acc[mt][nt], afr[mt], bfr[nt]);
        }
        __syncthreads();
    }

    // ---- Epilogue: per-row region min/argmin + extras within DELTA ----
    const int groupID = lane >> 2;
    const int tIdx    = lane & 3;
    const int colBase = nBase + warp_n * 64;
    const int region  = blockIdx.y * 2 + warp_n;

    float cn[8][2];
#pragma unroll
    for (int nt = 0; nt < 8; ++nt) {
        cn[nt][0] = __ldg(&g_cnorm[colBase + nt * 8 + tIdx * 2 + 0]);
        cn[nt][1] = __ldg(&g_cnorm[colBase + nt * 8 + tIdx * 2 + 1]);
    }

#pragma unroll
    for (int mt = 0; mt < 2; ++mt)
#pragma unroll
        for (int rh = 0; rh < 2; ++rh) {
            const int row = mBase + warp_m * 32 + mt * 16 + rh * 8 + groupID;
            float dv[8][2];
            float best = 3.4e38f;
            int bidx = 0;
#pragma unroll
            for (int nt = 0; nt < 8; ++nt)
#pragma unroll
                for (int jj = 0; jj < 2; ++jj) {
                    float d = cn[nt][jj] - 2.f * acc[mt][nt][rh * 2 + jj];
                    dv[nt][jj] = d;
                    int gi = colBase + nt * 8 + tIdx * 2 + jj;
                    if (d < best) { best = d; bidx = gi; }
                }
            // quad reduce (lanes groupID*4 + tIdx); all lanes converge
#pragma unroll
            for (int x = 1; x < 4; x <<= 1) {
                float od = __shfl_xor_sync(0xffffffffu, best, x);
                int   oi = __shfl_xor_sync(0xffffffffu, bidx, x);
                if (od < best || (od == best && oi < bidx)) { best = od; bidx = oi; }
            }
            if (tIdx == 0) {
                g_pd[(size_t)row * NREG + region] = best;
                g_pi[(size_t)row * NREG + region] = bidx;
            }
            // extras: values within DELTA of region min (excluding argmin)
            const float lim = best + DELTA;
#pragma unroll
            for (int nt = 0; nt < 8; ++nt)
#pragma unroll
                for (int jj = 0; jj < 2; ++jj) {
                    int gi = colBase + nt * 8 + tIdx * 2 + jj;
                    if (dv[nt][jj] <= lim && gi != bidx) {
                        int c = atomicAdd(&g_cnt[row], 1);
                        if (c < CAP) {
                            g_cv[(size_t)row * CAP + c] = dv[nt][jj];
                            g_ci[(size_t)row * CAP + c] = gi;
                        }
                    }
                }
        }
}

// ---------------------------------------------------------------------------
// Phase 2: per-token threshold + exact fp32 rescue + gather.
// One 128-thread block per token.
// Output layout: [tokens(4096) | quantized(4096*768)] float32.
// ---------------------------------------------------------------------------
#define MAXC 384
__global__ __launch_bounds__(128) void finalize(const float* __restrict__ rep,
                                                const float* __restrict__ cent,
                                                float* __restrict__ out) {
    __shared__ __align__(16) float srep[DDIM];
    __shared__ float wred[4];
    __shared__ float sthr;
    __shared__ int scand[MAXC];
    __shared__ int scn;
    __shared__ unsigned long long sbest;

    const int i = blockIdx.x;
    const int t = threadIdx.x;
    const int warpid = t >> 5;
    const int lane = t & 31;

    // rep row -> smem
    const int srow = i + (i >> 9) + 1;
    const float4* repv = (const float4*)(rep + (size_t)srow * DDIM);
#pragma unroll
    for (int q = 0; q < 2; ++q)
        if (t + q * 128 < DDIM / 4) ((float4*)srep)[t + q * 128] = repv[t + q * 128];
    if (t == 0) { scn = 0; sbest = ~0ull; }

    // dense region mins (coalesced: [token][region])
    const float dmin = g_pd[(size_t)i * NREG + t];
    float m = dmin;
#pragma unroll
    for (int off = 16; off; off >>= 1)
        m = fminf(m, __shfl_xor_sync(0xffffffffu, m, off));
    if (lane == 0) wred[warpid] = m;
    __syncthreads();
    if (t == 0) {
        float mm = fminf(fminf(wred[0], wred[1]), fminf(wred[2], wred[3]));
        sthr = mm + DELTA;
    }
    __syncthreads();
    const float thr = sthr;

    // collect candidates
    if (dmin <= thr) {
        int c = atomicAdd(&scn, 1);
        scand[c] = g_pi[(size_t)i * NREG + t];
    }
    int ec = g_cnt[i];
    if (ec > CAP) ec = CAP;
    for (int e = t; e < ec; e += 128)
        if (g_cv[(size_t)i * CAP + e] <= thr) {
            int c = atomicAdd(&scn, 1);
            if (c < MAXC) scand[c] = g_ci[(size_t)i * CAP + e];
        }
    __syncthreads();

    // exact fp32 rescue, one candidate per warp round-robin
    int nc = scn < MAXC ? scn : MAXC;
    for (int c = warpid; c < nc; c += 4) {
        const int k = scand[c];
        const float4* c4 = (const float4*)(cent + (size_t)k * DDIM);
        float s0 = 0.f, s1 = 0.f, s2 = 0.f, s3 = 0.f;
#pragma unroll
        for (int q = lane; q < DDIM / 4; q += 32) {
            float4 cv = __ldg(&c4[q]);
            float4 rv = ((const float4*)srep)[q];
            s0 = fmaf(rv.x, cv.x, s0);
            s1 = fmaf(rv.y, cv.y, s1);
            s2 = fmaf(rv.z, cv.z, s2);
            s3 = fmaf(rv.w, cv.w, s3);
        }
        float s = (s0 + s1) + (s2 + s3);
#pragma unroll
        for (int off = 16; off; off >>= 1) s += __shfl_xor_sync(0xffffffffu, s, off);
        if (lane == 0) {
            float d = __ldg(&g_cnorm[k]) - 2.f * s;
            unsigned int u = __float_as_uint(d);
            unsigned int key = (u & 0x80000000u) ? ~u : (u | 0x80000000u);
            unsigned long long pk = ((unsigned long long)key << 32) | (unsigned int)k;
            atomicMin(&sbest, pk);
        }
    }
    __syncthreads();

    const int kbest = (int)(sbest & 0xffffffffu);
    if (t == 0) out[i] = (float)kbest;
    const float4* src = (const float4*)(cent + (size_t)kbest * DDIM);
    float4* dst = (float4*)(out + NTOK + (size_t)i * DDIM);
#pragma unroll
    for (int q = 0; q < 2; ++q)
        if (t + q * 128 < DDIM / 4) dst[t + q * 128] = src[t + q * 128];
}

// ---------------------------------------------------------------------------
extern "C" void kernel_launch(void* const* d_in, const int* in_sizes, int n_in,
                              void* d_out, int out_size) {
    const float* rep  = (const float*)d_in[0];   // [8,513,768]
    const float* cent = (const float*)d_in[1];   // [8192,768]
    float* out = (float*)d_out;

    zero_cnt<<<NTOK / 256, 256>>>();
    conv_rep1<<<(size_t)NTOK * DDIM / 4 / 256, 256>>>(rep);
    conv_cent_norm<<<KCENT / 8, 256>>>(cent);

    dim3 g(NTOK / BM, KCENT / BN);
    vq_gemm<<<g, 256>>>();

    finalize<<<NTOK, 128>>>(rep, cent, out);
}